// round 17
// baseline (speedup 1.0000x reference)
#include <cuda_runtime.h>
#include <cuda_fp16.h>
#include <cstdint>

#define N_NODES 50000
#define NPAD    50048             // 391*128
#define EMB     128
#define R_REL   9
#define S_REL   18
#define NSLOT   19                // 18 relation slots + self
#define N_EDGES 800000
#define E2      (2*N_EDGES)
#define NSEG    (S_REL*N_NODES)   // 900000
#define YSTR    (NSLOT*EMB)       // 2432
#define TILES_M 391

// gemm smem: A(hi,lo) fixed + B(hi,lo) double-buffered; 128 rows x 128 s8, stride 144
#define SROW2   144
#define ATILE2  18432             // 128*144
#define OFF_AHI 0
#define OFF_ALO ATILE2
#define OFF_B   (2*ATILE2)        // 4 B tiles follow: [buf][hi/lo]
#define GEMM_DSM (6*ATILE2)       // 110592

#define S1 6.103515625e-5f        // 2^-14
#define S2 4.76837158203125e-7f   // 2^-21
#define YSCALE 0.015625f          // Y stored * 1/64 (fp16 overflow headroom)
#define YINV   64.0f

// -------- scratch (device globals) --------
__device__ int   g_cnt2[NSEG];
__device__ float g_alpha2[NSEG];
__device__ float g_gamma2[NSEG];
__device__ float g_A[N_NODES];
__device__ int   g_soff[NSEG + 1];
__device__ int   g_cur2[NSEG];
__device__ int   g_bsum[1024];
__device__ int   g_boff[1024];
__device__ int   g_rec[E2];
__device__ float4 g_meta[NSEG];              // {e0, e1, alpha, 0} per segment
__device__ float g_H[(size_t)N_NODES * EMB];
__device__ unsigned int g_Qxhi[NPAD * 32];   // X int8 hi (row = 128 bytes)
__device__ unsigned int g_Qxlo[NPAD * 32];
__device__ char  g_Pbhi[2 * NSLOT * EMB * EMB];   // [l][s][j][k] int8
__device__ char  g_Pblo[2 * NSLOT * EMB * EMB];
__device__ __half g_Y[(size_t)NPAD * YSTR];       // ~243 MB fp16 (scaled by 1/64)
__device__ float g_sa[N_NODES];
__device__ float g_sb[2 * NSLOT * EMB];

// ------------------------- PTX helpers -------------------------
__device__ __forceinline__ uint32_t smem_u32(const void* p) {
    uint32_t a;
    asm("{ .reg .u64 t; cvta.to.shared.u64 t, %1; cvt.u32.u64 %0, t; }" : "=r"(a) : "l"(p));
    return a;
}
__device__ __forceinline__ void cp_async16(uint32_t dst, const void* src) {
    asm volatile("cp.async.cg.shared.global [%0], [%1], 16;"
                 :: "r"(dst), "l"(src) : "memory");
}
#define CP_COMMIT() asm volatile("cp.async.commit_group;" ::: "memory")
#define CP_WAIT1()  asm volatile("cp.async.wait_group 1;" ::: "memory")
#define CP_WAIT0()  asm volatile("cp.async.wait_group 0;" ::: "memory")

__device__ __forceinline__ void ldsm_x4(uint32_t* r, uint32_t addr) {
    asm volatile("ldmatrix.sync.aligned.m8n8.x4.shared.b16 {%0,%1,%2,%3}, [%4];"
                 : "=r"(r[0]), "=r"(r[1]), "=r"(r[2]), "=r"(r[3]) : "r"(addr));
}
__device__ __forceinline__ void mma_s8(int* c, const uint32_t* a, const uint32_t* b) {
    asm volatile("mma.sync.aligned.m16n8k32.row.col.s32.s8.s8.s32 "
                 "{%0,%1,%2,%3}, {%4,%5,%6,%7}, {%8,%9}, {%0,%1,%2,%3};"
                 : "+r"(c[0]), "+r"(c[1]), "+r"(c[2]), "+r"(c[3])
                 : "r"(a[0]), "r"(a[1]), "r"(a[2]), "r"(a[3]), "r"(b[0]), "r"(b[1]));
}

__device__ __forceinline__ unsigned int prmt_pack(int a, int b, int c, int d) {
    unsigned int p01 = __byte_perm((unsigned int)a, (unsigned int)b, 0x0040);
    unsigned int p23 = __byte_perm((unsigned int)c, (unsigned int)d, 0x0040);
    return __byte_perm(p01, p23, 0x5410);
}
__device__ __forceinline__ void quant_fast(float v, float inv_sa, int& qh, int& ql) {
    float u = v * inv_sa;                         // |u| <= 1
    float s = fminf(fmaxf(u * 128.f, -127.f), 127.f);
    float qhf = rintf(s);
    qh = (int)qhf;
    float r1 = fmaf(qhf, -0.0078125f, u);
    ql = min(__float2int_rn(r1 * 16384.f), 127);
}

// ---------------------------- preprocessing (unchanged) ----------------------------
__global__ void zero_kernel() {
    for (int idx = blockIdx.x * blockDim.x + threadIdx.x; idx < NSEG;
         idx += gridDim.x * blockDim.x) g_cnt2[idx] = 0;
}

__global__ void hist_kernel(const int* __restrict__ ei, const int* __restrict__ et) {
    int idx = blockIdx.x * blockDim.x + threadIdx.x;
    if (idx >= E2) return;
    int dest, s;
    if (idx < N_EDGES) { dest = ei[idx]; s = et[idx]; }
    else { int e = idx - N_EDGES; dest = ei[N_EDGES + e]; s = et[e] + R_REL; }
    atomicAdd(&g_cnt2[dest * S_REL + s], 1);
}

__global__ void alpha_kernel() {
    int i = blockIdx.x * blockDim.x + threadIdx.x;
    if (i >= N_NODES) return;
    int cnt[S_REL];
#pragma unroll
    for (int s = 0; s < S_REL; s++) cnt[s] = g_cnt2[i * S_REL + s];
    float suffix = 1.0f;
#pragma unroll
    for (int k = S_REL - 1; k >= 0; k--) {
        int s = (k >> 1) + R_REL * (k & 1);
        int c = cnt[s];
        float f = 2.0f / (float)(c > 0 ? c : 1);
        suffix *= f;
        g_alpha2[i * S_REL + s] = suffix;
        g_gamma2[i * S_REL + s] = suffix * (float)c;
    }
    g_A[i] = suffix;
}

__global__ void scan1_kernel() {
    __shared__ int wsum[32];
    int b = blockIdx.x, t = threadIdx.x;
    int i = b * 1024 + t;
    int lane = t & 31, w = t >> 5;
    int v = (i < NSEG) ? g_cnt2[i] : 0;
    int val = v;
#pragma unroll
    for (int d = 1; d < 32; d <<= 1) {
        int u = __shfl_up_sync(0xFFFFFFFF, val, d);
        if (lane >= d) val += u;
    }
    if (lane == 31) wsum[w] = val;
    __syncthreads();
    if (w == 0) {
        int x = wsum[lane];
#pragma unroll
        for (int d = 1; d < 32; d <<= 1) {
            int u = __shfl_up_sync(0xFFFFFFFF, x, d);
            if (lane >= d) x += u;
        }
        wsum[lane] = x;
    }
    __syncthreads();
    int incl = val + (w > 0 ? wsum[w - 1] : 0);
    if (i < NSEG) g_soff[i + 1] = incl;
    if (t == 0) g_bsum[b] = wsum[31];
}
__global__ void scan2_kernel(int nb) {
    __shared__ int wsum[32];
    int t = threadIdx.x, lane = t & 31, w = t >> 5;
    int v = (t < nb) ? g_bsum[t] : 0;
    int val = v;
#pragma unroll
    for (int d = 1; d < 32; d <<= 1) {
        int u = __shfl_up_sync(0xFFFFFFFF, val, d);
        if (lane >= d) val += u;
    }
    if (lane == 31) wsum[w] = val;
    __syncthreads();
    if (w == 0) {
        int x = wsum[lane];
#pragma unroll
        for (int d = 1; d < 32; d <<= 1) {
            int u = __shfl_up_sync(0xFFFFFFFF, x, d);
            if (lane >= d) x += u;
        }
        wsum[lane] = x;
    }
    __syncthreads();
    int incl = val + (w > 0 ? wsum[w - 1] : 0);
    if (t < nb) g_boff[t] = incl - v;   // exclusive
}
__global__ void scan3_kernel() {
    int i = blockIdx.x * blockDim.x + threadIdx.x;
    if (i == 0) g_soff[0] = 0;
    if (i >= NSEG) return;
    int off = g_soff[i + 1] + g_boff[i >> 10];
    g_soff[i + 1] = off;
    int start = off - g_cnt2[i];
    g_cur2[i] = start;
    g_meta[i] = make_float4(__int_as_float(start), __int_as_float(off),
                            g_alpha2[i], 0.f);
}

__global__ void scatter_kernel(const int* __restrict__ ei, const int* __restrict__ et) {
    int idx = blockIdx.x * blockDim.x + threadIdx.x;
    if (idx >= E2) return;
    int dest, src, s;
    if (idx < N_EDGES) { dest = ei[idx]; src = ei[N_EDGES + idx]; s = et[idx]; }
    else { int e = idx - N_EDGES; dest = ei[N_EDGES + e]; src = ei[e]; s = et[e] + R_REL; }
    int pos = atomicAdd(&g_cur2[dest * S_REL + s], 1);
    g_rec[pos] = src;
}

// -------- weight quantization: per (layer, slot, out-col j) over K=128 --------
__global__ void __launch_bounds__(128) convw_kernel(const float* __restrict__ w) {
    __shared__ float red[128];
    int blk = blockIdx.x;              // (l*19+s)*128 + j
    int ls = blk >> 7, j = blk & 127;
    int t = threadIdx.x;               // k
    float v = w[((size_t)ls * EMB + t) * EMB + j];
    red[t] = fabsf(v);
    __syncthreads();
    for (int d = 64; d > 0; d >>= 1) {
        if (t < d) red[t] = fmaxf(red[t], red[t + d]);
        __syncthreads();
    }
    float sb = fmaxf(red[0], 1e-30f);
    if (t == 0) g_sb[ls * EMB + j] = sb;
    float inv = 1.f / sb;
    int qh, ql;
    quant_fast(v, inv, qh, ql);
    size_t idx = (size_t)(ls * EMB + j) * EMB + t;
    g_Pbhi[idx] = (char)qh;
    g_Pblo[idx] = (char)ql;
}

// -------- X quantization: warp per row, 128 values --------
__global__ void __launch_bounds__(256) quantx_kernel(const float* __restrict__ X) {
    int i = (blockIdx.x << 3) + (threadIdx.x >> 5);
    if (i >= N_NODES) return;
    int lane = threadIdx.x & 31;
    float4 v = *(const float4*)(X + (size_t)i * EMB + lane * 4);
    float m = fmaxf(fmaxf(fabsf(v.x), fabsf(v.y)), fmaxf(fabsf(v.z), fabsf(v.w)));
#pragma unroll
    for (int d = 16; d > 0; d >>= 1) m = fmaxf(m, __shfl_xor_sync(0xFFFFFFFF, m, d));
    float sa = fmaxf(m, 1e-30f);
    if (lane == 0) g_sa[i] = sa;
    float inv = 1.f / sa;
    int qh[4], ql[4];
    quant_fast(v.x, inv, qh[0], ql[0]);
    quant_fast(v.y, inv, qh[1], ql[1]);
    quant_fast(v.z, inv, qh[2], ql[2]);
    quant_fast(v.w, inv, qh[3], ql[3]);
    g_Qxhi[i * 32 + lane] = prmt_pack(qh[0], qh[1], qh[2], qh[3]);
    g_Qxlo[i * 32 + lane] = prmt_pack(ql[0], ql[1], ql[2], ql[3]);
}

// -------- GEMM: Y[m, s*128+j] = X[m,:] @ W_s[:,j], fp16 output scaled 1/64 --------
__global__ void __launch_bounds__(256) gemm9_kernel(int layer) {
    extern __shared__ char dsm[];
    uint32_t sb = smem_u32(dsm);
    int tid = threadIdx.x, wid = tid >> 5, lane = tid & 31;
    int warp_m = wid & 1;
    int warp_n = wid >> 1;
    int m0 = blockIdx.x * 128;

    const char* Bh = g_Pbhi + (size_t)layer * NSLOT * EMB * EMB;
    const char* Bl = g_Pblo + (size_t)layer * NSLOT * EMB * EMB;
    const char* Ah = (const char*)g_Qxhi;
    const char* Al = (const char*)g_Qxlo;

    uint32_t a_off = (uint32_t)((warp_m * 64 + (lane & 15)) * SROW2 + (lane >> 4) * 16);
    int bm = lane >> 3;
    uint32_t b_row = (uint32_t)(warp_n * 32 + ((bm >> 1) << 3) + (lane & 7));
    uint32_t b_koff = (uint32_t)((bm & 1) * 16);

    // load A tiles (hi+lo) + B slot 0
#pragma unroll
    for (int p = 0; p < 4; p++) {
        int idx = tid + p * 256;
        int rrow = idx >> 3, c = idx & 7;
        uint32_t d = (uint32_t)(rrow * SROW2 + c * 16);
        size_t asrc = (size_t)(m0 + rrow) * EMB + c * 16;
        cp_async16(sb + OFF_AHI + d, Ah + asrc);
        cp_async16(sb + OFF_ALO + d, Al + asrc);
        size_t bsrc = (size_t)rrow * EMB + c * 16;   // slot 0
        cp_async16(sb + OFF_B + d, Bh + bsrc);
        cp_async16(sb + OFF_B + ATILE2 + d, Bl + bsrc);
    }
    CP_COMMIT();

    // preload per-fragment-row scales (rows are slot-invariant): rows rbase+mi*16, +8
    int rbase = m0 + warp_m * 64 + (lane >> 2);
    float sar[4], sar8[4];
#pragma unroll
    for (int mi = 0; mi < 4; mi++) {
        int r = rbase + mi * 16;
        sar[mi]  = (r < N_NODES) ? g_sa[r] : 0.f;
        sar8[mi] = (r + 8 < N_NODES) ? g_sa[r + 8] : 0.f;
    }
    const float* sbl = g_sb + layer * NSLOT * EMB;

    for (int s = 0; s < NSLOT; s++) {
        if (s + 1 < NSLOT) {
            const char* bh = Bh + (size_t)(s + 1) * EMB * EMB;
            const char* bl = Bl + (size_t)(s + 1) * EMB * EMB;
            uint32_t bb = sb + OFF_B + ((s + 1) & 1) * (2 * ATILE2);
#pragma unroll
            for (int p = 0; p < 4; p++) {
                int idx = tid + p * 256;
                int rrow = idx >> 3, c = idx & 7;
                uint32_t d = (uint32_t)(rrow * SROW2 + c * 16);
                size_t bsrc = (size_t)rrow * EMB + c * 16;
                cp_async16(bb + d, bh + bsrc);
                cp_async16(bb + ATILE2 + d, bl + bsrc);
            }
            CP_COMMIT();
            CP_WAIT1();
        } else {
            CP_WAIT0();
        }
        __syncthreads();

        int acc1[4][4][4], acc2[4][4][4];
#pragma unroll
        for (int mi = 0; mi < 4; mi++)
#pragma unroll
            for (int ni = 0; ni < 4; ni++)
#pragma unroll
                for (int q = 0; q < 4; q++) { acc1[mi][ni][q] = 0; acc2[mi][ni][q] = 0; }

        uint32_t bbase = sb + OFF_B + (s & 1) * (2 * ATILE2);
#pragma unroll
        for (int ks = 0; ks < 4; ks++) {
            uint32_t k2 = (uint32_t)(ks * 32);
            uint32_t Ah4[4][4], Al4[4][4];
#pragma unroll
            for (int mi = 0; mi < 4; mi++) {
                uint32_t ad = sb + OFF_AHI + a_off + (uint32_t)(mi * 16 * SROW2) + k2;
                ldsm_x4(Ah4[mi], ad);
                ldsm_x4(Al4[mi], ad + (OFF_ALO - OFF_AHI));
            }
            uint32_t Bh4[4][2], Bl4[4][2];
#pragma unroll
            for (int nj = 0; nj < 2; nj++) {
                uint32_t bd = bbase + (b_row + nj * 16) * SROW2 + b_koff + k2;
                uint32_t r4[4];
                ldsm_x4(r4, bd);
                Bh4[nj * 2][0] = r4[0]; Bh4[nj * 2][1] = r4[1];
                Bh4[nj * 2 + 1][0] = r4[2]; Bh4[nj * 2 + 1][1] = r4[3];
                ldsm_x4(r4, bd + ATILE2);
                Bl4[nj * 2][0] = r4[0]; Bl4[nj * 2][1] = r4[1];
                Bl4[nj * 2 + 1][0] = r4[2]; Bl4[nj * 2 + 1][1] = r4[3];
            }
#pragma unroll
            for (int mi = 0; mi < 4; mi++)
#pragma unroll
                for (int ni = 0; ni < 4; ni++) {
                    mma_s8(acc1[mi][ni], Ah4[mi], Bh4[ni]);
                    mma_s8(acc2[mi][ni], Ah4[mi], Bl4[ni]);
                    mma_s8(acc2[mi][ni], Al4[mi], Bh4[ni]);
                }
        }
        __syncthreads();   // done reading this B buffer before its reuse

        // epilogue: dequant (x 1/64) -> fp16 -> Y
        int cbase = warp_n * 32 + (lane & 3) * 2;
        const float* sbp = sbl + s * EMB;
        float f1 = S1 * YSCALE, f2 = S2 * YSCALE;
#pragma unroll
        for (int mi = 0; mi < 4; mi++) {
            int r = rbase + mi * 16;
#pragma unroll
            for (int ni = 0; ni < 4; ni++) {
                int c = cbase + ni * 8;
                float c0 = sbp[c], c1 = sbp[c + 1];
                {
                    float vx = sar[mi] * c0 * ((float)acc1[mi][ni][0] * f1 + (float)acc2[mi][ni][0] * f2);
                    float vy = sar[mi] * c1 * ((float)acc1[mi][ni][1] * f1 + (float)acc2[mi][ni][1] * f2);
                    *(__half2*)(g_Y + (size_t)r * YSTR + s * EMB + c) =
                        __floats2half2_rn(vx, vy);
                }
                {
                    float vx = sar8[mi] * c0 * ((float)acc1[mi][ni][2] * f1 + (float)acc2[mi][ni][2] * f2);
                    float vy = sar8[mi] * c1 * ((float)acc1[mi][ni][3] * f1 + (float)acc2[mi][ni][3] * f2);
                    *(__half2*)(g_Y + (size_t)(r + 8) * YSTR + s * EMB + c) =
                        __floats2half2_rn(vx, vy);
                }
            }
        }
    }
}

// -------- node kernel: gather Y (fp16), weight, add biases, fp32 out --------
__global__ void __launch_bounds__(256) node9_kernel(const float* __restrict__ bl,
                                                    float* __restrict__ Out,
                                                    int do_relu) {
    int i = (blockIdx.x << 3) + (threadIdx.x >> 5);
    if (i >= N_NODES) return;
    int lane = threadIdx.x & 31;
    int fo = lane << 2;

    float Ai = g_A[i];
    float4 accY, accB;
    {
        uint2 yu = *(const uint2*)(g_Y + (size_t)i * YSTR + S_REL * EMB + fo);
        float2 y0 = __half22float2(*(__half2*)&yu.x);
        float2 y1 = __half22float2(*(__half2*)&yu.y);
        accY.x = Ai * y0.x; accY.y = Ai * y0.y;
        accY.z = Ai * y1.x; accY.w = Ai * y1.y;
        float4 b18 = *(const float4*)(bl + S_REL * EMB + fo);
        accB.x = Ai * b18.x; accB.y = Ai * b18.y;
        accB.z = Ai * b18.z; accB.w = Ai * b18.w;
    }
#pragma unroll 1
    for (int s = 0; s < S_REL; s++) {
        float4 m = g_meta[i * S_REL + s];
        int e0 = __float_as_int(m.x), e1 = __float_as_int(m.y);
        float al = m.z;
        float g = g_gamma2[i * S_REL + s];
        float4 bs = *(const float4*)(bl + s * EMB + fo);
        accB.x = fmaf(g, bs.x, accB.x);
        accB.y = fmaf(g, bs.y, accB.y);
        accB.z = fmaf(g, bs.z, accB.z);
        accB.w = fmaf(g, bs.w, accB.w);
        float4 a = make_float4(0.f, 0.f, 0.f, 0.f);
        for (int e = e0; e < e1; e++) {
            int src = g_rec[e];
            uint2 yu = *(const uint2*)(g_Y + (size_t)src * YSTR + (s << 7) + fo);
            float2 y0 = __half22float2(*(__half2*)&yu.x);
            float2 y1 = __half22float2(*(__half2*)&yu.y);
            a.x += y0.x; a.y += y0.y; a.z += y1.x; a.w += y1.y;
        }
        accY.x = fmaf(al, a.x, accY.x);
        accY.y = fmaf(al, a.y, accY.y);
        accY.z = fmaf(al, a.z, accY.z);
        accY.w = fmaf(al, a.w, accY.w);
    }
    float4 r;
    r.x = fmaf(YINV, accY.x, accB.x);
    r.y = fmaf(YINV, accY.y, accB.y);
    r.z = fmaf(YINV, accY.z, accB.z);
    r.w = fmaf(YINV, accY.w, accB.w);
    if (do_relu) {
        r.x = fmaxf(r.x, 0.f); r.y = fmaxf(r.y, 0.f);
        r.z = fmaxf(r.z, 0.f); r.w = fmaxf(r.w, 0.f);
    }
    *(float4*)(Out + (size_t)i * EMB + fo) = r;
}

// ------------------------------ launch ---------------------------------
extern "C" void kernel_launch(void* const* d_in, const int* in_sizes, int n_in,
                              void* d_out, int out_size) {
    const int*   ei  = (const int*)d_in[0];     // [2, E]
    const int*   et  = (const int*)d_in[1];     // [E]
    const float* emb = (const float*)d_in[2];   // [N, 128]
    const float* w   = (const float*)d_in[3];   // [2, 19, 128, 128]
    const float* b   = (const float*)d_in[4];   // [2, 19, 128]
    float* out = (float*)d_out;

    float* hptr = nullptr;
    cudaGetSymbolAddress((void**)&hptr, g_H);

    cudaFuncSetAttribute(gemm9_kernel,
                         cudaFuncAttributeMaxDynamicSharedMemorySize, GEMM_DSM);

    zero_kernel<<<512, 256>>>();
    hist_kernel<<<(E2 + 255) / 256, 256>>>(ei, et);
    alpha_kernel<<<(N_NODES + 255) / 256, 256>>>();
    int nb = (NSEG + 1023) / 1024;   // 879
    scan1_kernel<<<nb, 1024>>>();
    scan2_kernel<<<1, 1024>>>(nb);
    scan3_kernel<<<(NSEG + 255) / 256, 256>>>();
    scatter_kernel<<<(E2 + 255) / 256, 256>>>(ei, et);
    convw_kernel<<<2 * NSLOT * EMB, 128>>>(w);

    int qgrid = (N_NODES + 7) / 8;

    // layer 0: emb -> H (relu)
    quantx_kernel<<<qgrid, 256>>>(emb);
    gemm9_kernel<<<TILES_M, 256, GEMM_DSM>>>(0);
    node9_kernel<<<qgrid, 256>>>(b, hptr, 1);
    // layer 1: H -> out
    quantx_kernel<<<qgrid, 256>>>(hptr);
    gemm9_kernel<<<TILES_M, 256, GEMM_DSM>>>(1);
    node9_kernel<<<qgrid, 256>>>(b + NSLOT * EMB, out, 0);
}